// round 1
// baseline (speedup 1.0000x reference)
#include <cuda_runtime.h>

// Problem constants (fixed by setup_inputs)
#define N_   8192
#define YD_  512
#define XD_  64
#define K_   16
#define S_   10
#define NS_  (N_*S_)   // 81920
#define LOG2PI 1.8378770664093453

// ---- scratch (device globals; no runtime allocation) ----
__device__ float g_enc_mu[N_*XD_];
__device__ float g_enc_sig[N_*XD_];
__device__ float g_x[NS_*XD_];
__device__ double g_acc[4];   // 0: loss1 partial, 1: loss2+3+4 partial, 2: loss5

__global__ void init_acc_kernel() {
    if (threadIdx.x < 4) g_acc[threadIdx.x] = 0.0;
}

__device__ __forceinline__ float softplus_f(float v) {
    // log1p(exp(v)), numerically stable
    return fmaxf(v, 0.0f) + log1pf(__expf(-fabsf(v)));
}

// ============================================================
// Kernel 1: encoder GEMM.  C[8192,128] = Y @ [We_mu | We_sig]
// cols 0..63 -> enc_mu (+be_mu); cols 64..127 -> softplus(+be_sig)+1e-3
// Tile: 64 rows x 128 cols, BK=32, 256 threads (16x16), 4x8 per thread.
// ============================================================
__global__ void __launch_bounds__(256) encoder_kernel(
    const float* __restrict__ Y,
    const float* __restrict__ We_mu, const float* __restrict__ be_mu,
    const float* __restrict__ We_sig, const float* __restrict__ be_sig)
{
    __shared__ float As[32][65];
    __shared__ float Bs[32][128];
    int tid = threadIdx.x;
    int ty = tid >> 4, tx = tid & 15;
    int row0 = blockIdx.x * 64;

    float acc[4][8];
    #pragma unroll
    for (int i = 0; i < 4; i++)
        #pragma unroll
        for (int j = 0; j < 8; j++) acc[i][j] = 0.0f;

    for (int k0 = 0; k0 < YD_; k0 += 32) {
        #pragma unroll
        for (int it = 0; it < 8; it++) {
            int lin = it * 256 + tid;
            int r = lin >> 5, k = lin & 31;
            As[k][r] = Y[(row0 + r) * YD_ + k0 + k];
        }
        #pragma unroll
        for (int it = 0; it < 16; it++) {
            int lin = it * 256 + tid;
            int k = lin >> 7, c = lin & 127;
            Bs[k][c] = (c < 64) ? We_mu[(k0 + k) * XD_ + c]
                                : We_sig[(k0 + k) * XD_ + (c - 64)];
        }
        __syncthreads();
        #pragma unroll
        for (int k = 0; k < 32; k++) {
            float a[4], b[8];
            #pragma unroll
            for (int i = 0; i < 4; i++) a[i] = As[k][ty + 16 * i];
            #pragma unroll
            for (int j = 0; j < 8; j++) b[j] = Bs[k][tx + 16 * j];
            #pragma unroll
            for (int i = 0; i < 4; i++)
                #pragma unroll
                for (int j = 0; j < 8; j++)
                    acc[i][j] = fmaf(a[i], b[j], acc[i][j]);
        }
        __syncthreads();
    }
    #pragma unroll
    for (int i = 0; i < 4; i++) {
        int row = row0 + ty + 16 * i;
        #pragma unroll
        for (int j = 0; j < 8; j++) {
            int c = tx + 16 * j;
            if (c < 64) {
                g_enc_mu[row * XD_ + c] = acc[i][j] + be_mu[c];
            } else {
                int cc = c - 64;
                g_enc_sig[row * XD_ + cc] =
                    softplus_f(acc[i][j] + be_sig[cc]) + 1e-3f;
            }
        }
    }
}

// ============================================================
// Kernel 2: per-n fused GMM responsibilities + gumbel-softmax mixtures
// + x_samp + losses 2,3,4,5.  One block of 64 threads per n.
// ============================================================
__global__ void __launch_bounds__(64) mixture_kernel(
    const float* __restrict__ phi_mus, const float* __restrict__ phi_sigs,
    const float* __restrict__ phi_logits,
    const float* __restrict__ theta_mus, const float* __restrict__ theta_sigs,
    const float* __restrict__ theta_logits,
    const float* __restrict__ u_noise, const float* __restrict__ eps_noise,
    const float* __restrict__ temperature)
{
    int n = blockIdx.x;
    int tid = threadIdx.x;   // 0..63, thread = dimension d
    __shared__ float s_pmu[16 * 65], s_psg[16 * 65];
    __shared__ float s_tmu[16 * 65], s_tsg[16 * 65];
    __shared__ float s_mut[16 * 65], s_sgt[16 * 65];
    __shared__ float em[64], es[64], ies[64];
    __shared__ float lpi[16], lth[16];
    __shared__ float zl[16], zlp[16], zv[16];
    __shared__ float red[16][4];
    __shared__ float wred[2];

    int d = tid;
    float emd = g_enc_mu[n * XD_ + d];
    float esd = g_enc_sig[n * XD_ + d];
    em[d] = emd; es[d] = esd;
    float iesd = 1.0f / esd;
    ies[d] = iesd;

    #pragma unroll
    for (int k = 0; k < 16; k++) {
        s_pmu[k * 65 + d] = phi_mus[k * XD_ + d];
        s_psg[k * 65 + d] = phi_sigs[k * XD_ + d];
        s_tmu[k * 65 + d] = theta_mus[k * XD_ + d];
        s_tsg[k * 65 + d] = theta_sigs[k * XD_ + d];
    }
    if (tid == 0) {
        float m = -1e30f;
        for (int k = 0; k < 16; k++) m = fmaxf(m, phi_logits[k]);
        float sm = 0.0f;
        for (int k = 0; k < 16; k++) sm += __expf(phi_logits[k] - m);
        float lse = m + __logf(sm);
        for (int k = 0; k < 16; k++) lpi[k] = phi_logits[k] - lse;
    }
    if (tid == 1) {
        float m = -1e30f;
        for (int k = 0; k < 16; k++) m = fmaxf(m, theta_logits[k]);
        float sm = 0.0f;
        for (int k = 0; k < 16; k++) sm += __expf(theta_logits[k] - m);
        float lse = m + __logf(sm);
        for (int k = 0; k < 16; k++) lth[k] = theta_logits[k] - lse;
    }
    __syncthreads();

    // z_logits: 16 k x 4 groups of 16 dims
    {
        int k = tid >> 2, g = tid & 3;
        float a = 0.0f;
        #pragma unroll
        for (int i = 0; i < 16; i++) {
            int dd = g * 16 + i;
            float std = es[dd] + s_psg[k * 65 + dd];
            float t = __fdividef(em[dd] - s_pmu[k * 65 + dd], std);
            a += 0.5f * t * t + __logf(std);
        }
        red[k][g] = a;
    }
    __syncthreads();
    if (tid < 16) {
        int k = tid;
        zl[k] = lpi[k] - 0.5f * 64.0f * (float)LOG2PI
              - (red[k][0] + red[k][1] + red[k][2] + red[k][3]);
    }
    __syncthreads();

    float l5 = 0.0f;
    if (tid == 0) {
        float m = -1e30f;
        for (int k = 0; k < 16; k++) m = fmaxf(m, zl[k]);
        float sm = 0.0f;
        for (int k = 0; k < 16; k++) sm += __expf(zl[k] - m);
        float lse = m + __logf(sm);
        for (int k = 0; k < 16; k++) zlp[k] = zl[k] - lse;
        float s2 = 0.0f;
        for (int k = 0; k < 16; k++) s2 += __expf(zlp[k]);
        l5 = __logf(s2);
    }

    // per-cluster posterior mu_t / Sig_t
    #pragma unroll
    for (int k = 0; k < 16; k++) {
        float ig = 1.0f / s_psg[k * 65 + d];
        float st = 1.0f / (iesd + ig);
        s_sgt[k * 65 + d] = st;
        s_mut[k * 65 + d] = st * (iesd * emd + ig * s_pmu[k * 65 + d]);
    }
    __syncthreads();

    float invT = 1.0f / temperature[0];
    float lacc = 0.0f;
    float dotacc = 0.0f;
    const float* urow = u_noise + n * (S_ * K_);

    for (int s = 0; s < S_; s++) {
        if (tid < 16) {
            float uu = urow[s * 16 + tid];
            float gg = -__logf(-__logf(uu));
            zv[tid] = (zlp[tid] + gg) * invT;
        }
        __syncthreads();
        if (tid == 0) {
            float m = -1e30f;
            for (int k = 0; k < 16; k++) m = fmaxf(m, zv[k]);
            float e[16]; float sm = 0.0f;
            for (int k = 0; k < 16; k++) { e[k] = __expf(zv[k] - m); sm += e[k]; }
            float inv = 1.0f / sm;
            float dt = 0.0f;
            for (int k = 0; k < 16; k++) {
                float z = e[k] * inv;
                zv[k] = z;
                dt = fmaf(z, lth[k] - zlp[k], dt);
            }
            dotacc += dt;
        }
        __syncthreads();

        float ms = 0, ssg = 0, tm = 0, tsg = 0, pm = 0, psg = 0;
        #pragma unroll
        for (int k = 0; k < 16; k++) {
            float z = zv[k];
            ms  = fmaf(z, s_mut[k * 65 + d], ms);
            ssg = fmaf(z, s_sgt[k * 65 + d], ssg);
            tm  = fmaf(z, s_tmu[k * 65 + d], tm);
            tsg = fmaf(z, s_tsg[k * 65 + d], tsg);
            pm  = fmaf(z, s_pmu[k * 65 + d], pm);
            psg = fmaf(z, s_psg[k * 65 + d], psg);
        }
        int row = n * S_ + s;
        float x = fmaf(sqrtf(ssg), eps_noise[row * XD_ + d], ms);
        g_x[row * XD_ + d] = x;
        float te = (x - emd) * iesd;
        float tt = __fdividef(x - tm, tsg);
        float tp = __fdividef(x - pm, psg);
        // loss2+loss3+loss4 per-dim terms (row constants handled at finalize)
        lacc += 0.5f * (te * te - tt * tt + tp * tp)
              - __logf(tsg) + __logf(psg);
        __syncthreads();
    }
    lacc += (float)S_ * __logf(esd);   // He term, constant over s

    #pragma unroll
    for (int o = 16; o > 0; o >>= 1)
        lacc += __shfl_down_sync(0xffffffffu, lacc, o);
    if ((tid & 31) == 0) wred[tid >> 5] = lacc;
    __syncthreads();
    if (tid == 0) {
        double tot = (double)(wred[0] + wred[1]) + (double)dotacc;
        atomicAdd(&g_acc[1], tot);
        atomicAdd(&g_acc[2], (double)l5);
    }
}

// ============================================================
// Kernel 3: decoder GEMMs fused with loss1 reduction.
// Tile 64 rows x 128 cols, BK=32 (two chunks over K=64), 256 threads.
// mu_y / sig_y never hit global memory.
// ============================================================
__global__ void __launch_bounds__(256) decoder_kernel(
    const float* __restrict__ Y,
    const float* __restrict__ Wd_mu, const float* __restrict__ bd_mu,
    const float* __restrict__ Wd_sig, const float* __restrict__ bd_sig)
{
    __shared__ float As[32][65];
    __shared__ float Bmu[32][128];
    __shared__ float Bsg[32][128];
    __shared__ float warp_red[8];
    int tid = threadIdx.x;
    int ty = tid >> 4, tx = tid & 15;
    int row0 = blockIdx.x * 64;
    int j0 = blockIdx.y * 128;

    float amu[4][8], asg[4][8];
    #pragma unroll
    for (int i = 0; i < 4; i++)
        #pragma unroll
        for (int j = 0; j < 8; j++) { amu[i][j] = 0.0f; asg[i][j] = 0.0f; }

    #pragma unroll
    for (int kc = 0; kc < 2; kc++) {
        #pragma unroll
        for (int it = 0; it < 8; it++) {
            int lin = it * 256 + tid;
            int r = lin >> 5, k = lin & 31;
            As[k][r] = g_x[(row0 + r) * XD_ + kc * 32 + k];
        }
        #pragma unroll
        for (int it = 0; it < 16; it++) {
            int lin = it * 256 + tid;
            int k = lin >> 7, c = lin & 127;
            int gk = (kc * 32 + k) * YD_ + j0 + c;
            Bmu[k][c] = Wd_mu[gk];
            Bsg[k][c] = Wd_sig[gk];
        }
        __syncthreads();
        #pragma unroll
        for (int k = 0; k < 32; k++) {
            float a[4], bm[8], bs[8];
            #pragma unroll
            for (int i = 0; i < 4; i++) a[i] = As[k][ty + 16 * i];
            #pragma unroll
            for (int j = 0; j < 8; j++) {
                bm[j] = Bmu[k][tx + 16 * j];
                bs[j] = Bsg[k][tx + 16 * j];
            }
            #pragma unroll
            for (int i = 0; i < 4; i++)
                #pragma unroll
                for (int j = 0; j < 8; j++) {
                    amu[i][j] = fmaf(a[i], bm[j], amu[i][j]);
                    asg[i][j] = fmaf(a[i], bs[j], asg[i][j]);
                }
        }
        __syncthreads();
    }

    // fused loss1 epilogue
    float part = 0.0f;
    #pragma unroll
    for (int i = 0; i < 4; i++) {
        int row = row0 + ty + 16 * i;
        int n = row / S_;
        const float* yrow = Y + n * YD_;
        #pragma unroll
        for (int j = 0; j < 8; j++) {
            int col = j0 + tx + 16 * j;
            float mu = amu[i][j] + bd_mu[col];
            float sg = softplus_f(asg[i][j] + bd_sig[col]) + 1e-3f;
            float t = __fdividef(yrow[col] - mu, sg);
            part += -0.5f * t * t - __logf(sg);
        }
    }
    #pragma unroll
    for (int o = 16; o > 0; o >>= 1)
        part += __shfl_down_sync(0xffffffffu, part, o);
    if ((tid & 31) == 0) warp_red[tid >> 5] = part;
    __syncthreads();
    if (tid == 0) {
        float tot = 0.0f;
        #pragma unroll
        for (int w = 0; w < 8; w++) tot += warp_red[w];
        atomicAdd(&g_acc[0], (double)tot);
    }
}

// ============================================================
// Kernel 4: finalize. Adds analytic per-row constants, combines.
// ============================================================
__global__ void finalize_kernel(float* out) {
    double NSd = (double)NS_;
    double L1   = g_acc[0] - 0.5 * (double)YD_ * LOG2PI * NSd;
    double L234 = g_acc[1] + 0.5 * (double)XD_ * LOG2PI * NSd;
    double tot = (L1 + L234) / (double)S_ + g_acc[2];
    out[0] = (float)(-tot);
}

extern "C" void kernel_launch(void* const* d_in, const int* in_sizes, int n_in,
                              void* d_out, int out_size)
{
    const float* Y            = (const float*)d_in[0];
    const float* We_mu        = (const float*)d_in[1];
    const float* be_mu        = (const float*)d_in[2];
    const float* We_sig       = (const float*)d_in[3];
    const float* be_sig       = (const float*)d_in[4];
    const float* Wd_mu        = (const float*)d_in[5];
    const float* bd_mu        = (const float*)d_in[6];
    const float* Wd_sig       = (const float*)d_in[7];
    const float* bd_sig       = (const float*)d_in[8];
    const float* phi_mus      = (const float*)d_in[9];
    const float* phi_sigs     = (const float*)d_in[10];
    const float* phi_logits   = (const float*)d_in[11];
    const float* theta_mus    = (const float*)d_in[12];
    const float* theta_sigs   = (const float*)d_in[13];
    const float* theta_logits = (const float*)d_in[14];
    const float* u_noise      = (const float*)d_in[15];
    const float* eps_noise    = (const float*)d_in[16];
    const float* temperature  = (const float*)d_in[17];

    init_acc_kernel<<<1, 32>>>();
    encoder_kernel<<<N_ / 64, 256>>>(Y, We_mu, be_mu, We_sig, be_sig);
    mixture_kernel<<<N_, 64>>>(phi_mus, phi_sigs, phi_logits,
                               theta_mus, theta_sigs, theta_logits,
                               u_noise, eps_noise, temperature);
    decoder_kernel<<<dim3(NS_ / 64, YD_ / 128), 256>>>(Y, Wd_mu, bd_mu,
                                                       Wd_sig, bd_sig);
    finalize_kernel<<<1, 1>>>((float*)d_out);
}

// round 2
// speedup vs baseline: 2.1949x; 2.1949x over previous
#include <cuda_runtime.h>
#include <cstdint>

// Problem constants (fixed by setup_inputs)
#define N_   8192
#define YD_  512
#define XD_  64
#define K_   16
#define S_   10
#define NS_  (N_*S_)   // 81920
#define LOG2PI 1.8378770664093453

// ---- scratch (device globals; no runtime allocation) ----
__device__ float g_enc_mu[N_*XD_];
__device__ float g_enc_sig[N_*XD_];
__device__ float g_x[NS_*XD_];
__device__ double g_acc[4];   // 0: loss1 partial, 1: loss2+3+4 partial, 2: loss5

__global__ void init_acc_kernel() {
    if (threadIdx.x < 4) g_acc[threadIdx.x] = 0.0;
}

__device__ __forceinline__ float softplus_f(float v) {
    return fmaxf(v, 0.0f) + log1pf(__expf(-fabsf(v)));
}

__device__ __forceinline__ uint32_t to_tf32(float x) {
    uint32_t r;
    asm("cvt.rna.tf32.f32 %0, %1;" : "=r"(r) : "f"(x));
    return r;
}

// ============================================================
// Kernel 1: encoder GEMM.  C[8192,128] = Y @ [We_mu | We_sig]
// ============================================================
__global__ void __launch_bounds__(256) encoder_kernel(
    const float* __restrict__ Y,
    const float* __restrict__ We_mu, const float* __restrict__ be_mu,
    const float* __restrict__ We_sig, const float* __restrict__ be_sig)
{
    __shared__ float As[32][65];
    __shared__ float Bs[32][128];
    int tid = threadIdx.x;
    int ty = tid >> 4, tx = tid & 15;
    int row0 = blockIdx.x * 64;

    float acc[4][8];
    #pragma unroll
    for (int i = 0; i < 4; i++)
        #pragma unroll
        for (int j = 0; j < 8; j++) acc[i][j] = 0.0f;

    for (int k0 = 0; k0 < YD_; k0 += 32) {
        #pragma unroll
        for (int it = 0; it < 8; it++) {
            int lin = it * 256 + tid;
            int r = lin >> 5, k = lin & 31;
            As[k][r] = Y[(row0 + r) * YD_ + k0 + k];
        }
        #pragma unroll
        for (int it = 0; it < 16; it++) {
            int lin = it * 256 + tid;
            int k = lin >> 7, c = lin & 127;
            Bs[k][c] = (c < 64) ? We_mu[(k0 + k) * XD_ + c]
                                : We_sig[(k0 + k) * XD_ + (c - 64)];
        }
        __syncthreads();
        #pragma unroll
        for (int k = 0; k < 32; k++) {
            float a[4], b[8];
            #pragma unroll
            for (int i = 0; i < 4; i++) a[i] = As[k][ty + 16 * i];
            #pragma unroll
            for (int j = 0; j < 8; j++) b[j] = Bs[k][tx + 16 * j];
            #pragma unroll
            for (int i = 0; i < 4; i++)
                #pragma unroll
                for (int j = 0; j < 8; j++)
                    acc[i][j] = fmaf(a[i], b[j], acc[i][j]);
        }
        __syncthreads();
    }
    #pragma unroll
    for (int i = 0; i < 4; i++) {
        int row = row0 + ty + 16 * i;
        #pragma unroll
        for (int j = 0; j < 8; j++) {
            int c = tx + 16 * j;
            if (c < 64) {
                g_enc_mu[row * XD_ + c] = acc[i][j] + be_mu[c];
            } else {
                int cc = c - 64;
                g_enc_sig[row * XD_ + cc] =
                    softplus_f(acc[i][j] + be_sig[cc]) + 1e-3f;
            }
        }
    }
}

// ============================================================
// Kernel 2: per-n fused GMM responsibilities + gumbel-softmax mixtures
// + x_samp + losses 2,3,4,5.  One block of 64 threads per n.
// v2: parallel per-s softmax + k-outer mixture loop (4x fewer LDS).
// ============================================================
__global__ void __launch_bounds__(64) mixture_kernel(
    const float* __restrict__ phi_mus, const float* __restrict__ phi_sigs,
    const float* __restrict__ phi_logits,
    const float* __restrict__ theta_mus, const float* __restrict__ theta_sigs,
    const float* __restrict__ theta_logits,
    const float* __restrict__ u_noise, const float* __restrict__ eps_noise,
    const float* __restrict__ temperature)
{
    int n = blockIdx.x;
    int tid = threadIdx.x;   // 0..63, thread = dimension d
    __shared__ float s_pmu[16 * 65], s_psg[16 * 65];
    __shared__ float s_tmu[16 * 65], s_tsg[16 * 65];
    __shared__ float s_mut[16 * 65], s_sgt[16 * 65];
    __shared__ float em[64], es[64];
    __shared__ float lpi[16], lth[16];
    __shared__ float zl[16], zlp[16];
    __shared__ float s_z[S_][17];
    __shared__ float sdt[S_];
    __shared__ float red[16][4];
    __shared__ float wred[2];
    __shared__ float sl5;

    int d = tid;
    float emd = g_enc_mu[n * XD_ + d];
    float esd = g_enc_sig[n * XD_ + d];
    em[d] = emd; es[d] = esd;
    float iesd = 1.0f / esd;

    #pragma unroll
    for (int k = 0; k < 16; k++) {
        s_pmu[k * 65 + d] = phi_mus[k * XD_ + d];
        s_psg[k * 65 + d] = phi_sigs[k * XD_ + d];
        s_tmu[k * 65 + d] = theta_mus[k * XD_ + d];
        s_tsg[k * 65 + d] = theta_sigs[k * XD_ + d];
    }
    if (tid == 0) {
        float m = -1e30f;
        for (int k = 0; k < 16; k++) m = fmaxf(m, phi_logits[k]);
        float sm = 0.0f;
        for (int k = 0; k < 16; k++) sm += __expf(phi_logits[k] - m);
        float lse = m + __logf(sm);
        for (int k = 0; k < 16; k++) lpi[k] = phi_logits[k] - lse;
    }
    if (tid == 1) {
        float m = -1e30f;
        for (int k = 0; k < 16; k++) m = fmaxf(m, theta_logits[k]);
        float sm = 0.0f;
        for (int k = 0; k < 16; k++) sm += __expf(theta_logits[k] - m);
        float lse = m + __logf(sm);
        for (int k = 0; k < 16; k++) lth[k] = theta_logits[k] - lse;
    }
    __syncthreads();

    // z_logits: 16 k x 4 groups of 16 dims
    {
        int k = tid >> 2, g = tid & 3;
        float a = 0.0f;
        #pragma unroll
        for (int i = 0; i < 16; i++) {
            int dd = g * 16 + i;
            float std = es[dd] + s_psg[k * 65 + dd];
            float t = __fdividef(em[dd] - s_pmu[k * 65 + dd], std);
            a += 0.5f * t * t + __logf(std);
        }
        red[k][g] = a;
    }
    __syncthreads();
    if (tid < 16) {
        int k = tid;
        zl[k] = lpi[k] - 0.5f * 64.0f * (float)LOG2PI
              - (red[k][0] + red[k][1] + red[k][2] + red[k][3]);
    }
    __syncthreads();

    if (tid == 0) {
        float m = -1e30f;
        for (int k = 0; k < 16; k++) m = fmaxf(m, zl[k]);
        float sm = 0.0f;
        for (int k = 0; k < 16; k++) sm += __expf(zl[k] - m);
        float lse = m + __logf(sm);
        for (int k = 0; k < 16; k++) zlp[k] = zl[k] - lse;
        float s2 = 0.0f;
        for (int k = 0; k < 16; k++) s2 += __expf(zlp[k]);
        sl5 = __logf(s2);
    }

    // per-cluster posterior mu_t / Sig_t
    #pragma unroll
    for (int k = 0; k < 16; k++) {
        float ig = 1.0f / s_psg[k * 65 + d];
        float st = 1.0f / (iesd + ig);
        s_sgt[k * 65 + d] = st;
        s_mut[k * 65 + d] = st * (iesd * emd + ig * s_pmu[k * 65 + d]);
    }
    __syncthreads();

    // parallel gumbel-softmax: one thread per sample s
    float invT = 1.0f / temperature[0];
    if (tid < S_) {
        int s = tid;
        const float* urow = u_noise + n * (S_ * K_) + s * K_;
        float v[16];
        float m = -1e30f;
        #pragma unroll
        for (int k = 0; k < 16; k++) {
            float gg = -__logf(-__logf(urow[k]));
            v[k] = (zlp[k] + gg) * invT;
            m = fmaxf(m, v[k]);
        }
        float sm = 0.0f;
        #pragma unroll
        for (int k = 0; k < 16; k++) { v[k] = __expf(v[k] - m); sm += v[k]; }
        float inv = 1.0f / sm;
        float dt = 0.0f;
        #pragma unroll
        for (int k = 0; k < 16; k++) {
            float z = v[k] * inv;
            s_z[s][k] = z;
            dt = fmaf(z, lth[k] - zlp[k], dt);
        }
        sdt[s] = dt;
    }
    __syncthreads();

    // mixture accumulation, k-outer (table reads hoisted out of s-loop)
    float ms[S_], ssg[S_], tm[S_], tsg[S_], pm[S_], psg[S_];
    #pragma unroll
    for (int s = 0; s < S_; s++) {
        ms[s] = 0.f; ssg[s] = 0.f; tm[s] = 0.f;
        tsg[s] = 0.f; pm[s] = 0.f; psg[s] = 0.f;
    }
    #pragma unroll
    for (int k = 0; k < 16; k++) {
        float mut = s_mut[k * 65 + d];
        float sgt = s_sgt[k * 65 + d];
        float tmu = s_tmu[k * 65 + d];
        float tsig = s_tsg[k * 65 + d];
        float pmu = s_pmu[k * 65 + d];
        float psig = s_psg[k * 65 + d];
        #pragma unroll
        for (int s = 0; s < S_; s++) {
            float z = s_z[s][k];
            ms[s]  = fmaf(z, mut, ms[s]);
            ssg[s] = fmaf(z, sgt, ssg[s]);
            tm[s]  = fmaf(z, tmu, tm[s]);
            tsg[s] = fmaf(z, tsig, tsg[s]);
            pm[s]  = fmaf(z, pmu, pm[s]);
            psg[s] = fmaf(z, psig, psg[s]);
        }
    }

    float lacc = 0.0f;
    #pragma unroll
    for (int s = 0; s < S_; s++) {
        int row = n * S_ + s;
        float x = fmaf(sqrtf(ssg[s]), eps_noise[row * XD_ + d], ms[s]);
        g_x[row * XD_ + d] = x;
        float te = (x - emd) * iesd;
        float tt = __fdividef(x - tm[s], tsg[s]);
        float tp = __fdividef(x - pm[s], psg[s]);
        lacc += 0.5f * (te * te - tt * tt + tp * tp)
              - __logf(tsg[s]) + __logf(psg[s]);
    }
    lacc += (float)S_ * __logf(esd);   // He term, constant over s

    #pragma unroll
    for (int o = 16; o > 0; o >>= 1)
        lacc += __shfl_down_sync(0xffffffffu, lacc, o);
    if ((tid & 31) == 0) wred[tid >> 5] = lacc;
    __syncthreads();
    if (tid == 0) {
        float dts = 0.0f;
        #pragma unroll
        for (int s = 0; s < S_; s++) dts += sdt[s];
        double tot = (double)(wred[0] + wred[1]) + (double)dts;
        atomicAdd(&g_acc[1], tot);
        atomicAdd(&g_acc[2], (double)sl5);
    }
}

// ============================================================
// Kernel 3: tf32 tensor-core decoder GEMMs fused with loss1.
// Block tile 128(M) x 64(N), full K=64 in smem, 8 warps (4M x 2N).
// mu_y / sig_y never hit global memory.
// ============================================================
#define BM 128
#define BN 64
#define PA 68
#define PB 72
#define DEC_SMEM_FLOATS (BM*PA + 2*64*PB + 2*BN)

#define MMA_TF32(C, A, B0, B1)                                         \
    asm volatile(                                                      \
        "mma.sync.aligned.m16n8k8.row.col.f32.tf32.tf32.f32 "          \
        "{%0,%1,%2,%3}, {%4,%5,%6,%7}, {%8,%9}, {%0,%1,%2,%3};"        \
        : "+f"(C[0]), "+f"(C[1]), "+f"(C[2]), "+f"(C[3])               \
        : "r"(A[0]), "r"(A[1]), "r"(A[2]), "r"(A[3]), "r"(B0), "r"(B1))

__global__ void __launch_bounds__(256) decoder_kernel(
    const float* __restrict__ Y,
    const float* __restrict__ Wd_mu, const float* __restrict__ bd_mu,
    const float* __restrict__ Wd_sig, const float* __restrict__ bd_sig)
{
    extern __shared__ float smem[];
    float* sA  = smem;                 // [BM][PA]
    float* sBm = sA + BM * PA;         // [64][PB]
    float* sBs = sBm + 64 * PB;        // [64][PB]
    float* sbm = sBs + 64 * PB;        // [BN]
    float* sbs = sbm + BN;             // [BN]
    __shared__ float warp_red[8];

    int tid = threadIdx.x;
    int warp = tid >> 5, lane = tid & 31;
    int row0 = blockIdx.x * BM;        // NS-row offset
    int col0 = blockIdx.y * BN;        // Yd-col offset

    // --- stage A (g_x tile, tf32-converted) ---
    #pragma unroll
    for (int i = tid; i < BM * XD_ / 4; i += 256) {
        int r = i >> 4;
        int c4 = (i & 15) << 2;
        float4 v = *(const float4*)(g_x + (row0 + r) * XD_ + c4);
        sA[r * PA + c4 + 0] = __uint_as_float(to_tf32(v.x));
        sA[r * PA + c4 + 1] = __uint_as_float(to_tf32(v.y));
        sA[r * PA + c4 + 2] = __uint_as_float(to_tf32(v.z));
        sA[r * PA + c4 + 3] = __uint_as_float(to_tf32(v.w));
    }
    // --- stage B (weight slices, tf32-converted, [k][n]) ---
    #pragma unroll
    for (int i = tid; i < 64 * BN / 4; i += 256) {
        int k = i >> 4;
        int c4 = (i & 15) << 2;
        float4 vm = *(const float4*)(Wd_mu + k * YD_ + col0 + c4);
        float4 vs = *(const float4*)(Wd_sig + k * YD_ + col0 + c4);
        sBm[k * PB + c4 + 0] = __uint_as_float(to_tf32(vm.x));
        sBm[k * PB + c4 + 1] = __uint_as_float(to_tf32(vm.y));
        sBm[k * PB + c4 + 2] = __uint_as_float(to_tf32(vm.z));
        sBm[k * PB + c4 + 3] = __uint_as_float(to_tf32(vm.w));
        sBs[k * PB + c4 + 0] = __uint_as_float(to_tf32(vs.x));
        sBs[k * PB + c4 + 1] = __uint_as_float(to_tf32(vs.y));
        sBs[k * PB + c4 + 2] = __uint_as_float(to_tf32(vs.z));
        sBs[k * PB + c4 + 3] = __uint_as_float(to_tf32(vs.w));
    }
    if (tid < BN) {
        sbm[tid] = bd_mu[col0 + tid];
        sbs[tid] = bd_sig[col0 + tid];
    }
    __syncthreads();

    int wm = warp & 3;          // 4 M-warps
    int wn = warp >> 2;         // 2 N-warps
    int mBase = wm * 32;
    int nBase = wn * 32;
    int g = lane >> 2, tg = lane & 3;

    float cm[2][4][4], cs[2][4][4];
    #pragma unroll
    for (int mt = 0; mt < 2; mt++)
        #pragma unroll
        for (int nt = 0; nt < 4; nt++)
            #pragma unroll
            for (int r = 0; r < 4; r++) { cm[mt][nt][r] = 0.f; cs[mt][nt][r] = 0.f; }

    #pragma unroll
    for (int ks = 0; ks < 8; ks++) {
        int k0 = ks * 8;
        uint32_t a[2][4];
        #pragma unroll
        for (int mt = 0; mt < 2; mt++) {
            int r = mBase + mt * 16 + g;
            a[mt][0] = __float_as_uint(sA[r * PA + k0 + tg]);
            a[mt][1] = __float_as_uint(sA[(r + 8) * PA + k0 + tg]);
            a[mt][2] = __float_as_uint(sA[r * PA + k0 + tg + 4]);
            a[mt][3] = __float_as_uint(sA[(r + 8) * PA + k0 + tg + 4]);
        }
        #pragma unroll
        for (int nt = 0; nt < 4; nt++) {
            int c = nBase + nt * 8 + g;
            uint32_t bm0 = __float_as_uint(sBm[(k0 + tg) * PB + c]);
            uint32_t bm1 = __float_as_uint(sBm[(k0 + tg + 4) * PB + c]);
            uint32_t bs0 = __float_as_uint(sBs[(k0 + tg) * PB + c]);
            uint32_t bs1 = __float_as_uint(sBs[(k0 + tg + 4) * PB + c]);
            #pragma unroll
            for (int mt = 0; mt < 2; mt++) {
                MMA_TF32(cm[mt][nt], a[mt], bm0, bm1);
                MMA_TF32(cs[mt][nt], a[mt], bs0, bs1);
            }
        }
    }

    // --- fused loss1 epilogue ---
    float part = 0.0f;
    #pragma unroll
    for (int mt = 0; mt < 2; mt++) {
        #pragma unroll
        for (int half = 0; half < 2; half++) {
            int row = row0 + mBase + mt * 16 + g + half * 8;
            int n = row / S_;
            const float* yrow = Y + n * YD_;
            #pragma unroll
            for (int nt = 0; nt < 4; nt++) {
                #pragma unroll
                for (int p = 0; p < 2; p++) {
                    int r = half * 2 + p;
                    int cl = nBase + nt * 8 + tg * 2 + p;
                    float mu = cm[mt][nt][r] + sbm[cl];
                    float sg = softplus_f(cs[mt][nt][r] + sbs[cl]) + 1e-3f;
                    float t = __fdividef(yrow[col0 + cl] - mu, sg);
                    part += -0.5f * t * t - __logf(sg);
                }
            }
        }
    }
    #pragma unroll
    for (int o = 16; o > 0; o >>= 1)
        part += __shfl_down_sync(0xffffffffu, part, o);
    if (lane == 0) warp_red[warp] = part;
    __syncthreads();
    if (tid == 0) {
        float tot = 0.0f;
        #pragma unroll
        for (int w = 0; w < 8; w++) tot += warp_red[w];
        atomicAdd(&g_acc[0], (double)tot);
    }
}

// ============================================================
// Kernel 4: finalize.
// ============================================================
__global__ void finalize_kernel(float* out) {
    double NSd = (double)NS_;
    double L1   = g_acc[0] - 0.5 * (double)YD_ * LOG2PI * NSd;
    double L234 = g_acc[1] + 0.5 * (double)XD_ * LOG2PI * NSd;
    double tot = (L1 + L234) / (double)S_ + g_acc[2];
    out[0] = (float)(-tot);
}

extern "C" void kernel_launch(void* const* d_in, const int* in_sizes, int n_in,
                              void* d_out, int out_size)
{
    const float* Y            = (const float*)d_in[0];
    const float* We_mu        = (const float*)d_in[1];
    const float* be_mu        = (const float*)d_in[2];
    const float* We_sig       = (const float*)d_in[3];
    const float* be_sig       = (const float*)d_in[4];
    const float* Wd_mu        = (const float*)d_in[5];
    const float* bd_mu        = (const float*)d_in[6];
    const float* Wd_sig       = (const float*)d_in[7];
    const float* bd_sig       = (const float*)d_in[8];
    const float* phi_mus      = (const float*)d_in[9];
    const float* phi_sigs     = (const float*)d_in[10];
    const float* phi_logits   = (const float*)d_in[11];
    const float* theta_mus    = (const float*)d_in[12];
    const float* theta_sigs   = (const float*)d_in[13];
    const float* theta_logits = (const float*)d_in[14];
    const float* u_noise      = (const float*)d_in[15];
    const float* eps_noise    = (const float*)d_in[16];
    const float* temperature  = (const float*)d_in[17];

    static const size_t dec_smem = DEC_SMEM_FLOATS * sizeof(float);
    cudaFuncSetAttribute(decoder_kernel,
                         cudaFuncAttributeMaxDynamicSharedMemorySize,
                         (int)dec_smem);

    init_acc_kernel<<<1, 32>>>();
    encoder_kernel<<<N_ / 64, 256>>>(Y, We_mu, be_mu, We_sig, be_sig);
    mixture_kernel<<<N_, 64>>>(phi_mus, phi_sigs, phi_logits,
                               theta_mus, theta_sigs, theta_logits,
                               u_noise, eps_noise, temperature);
    decoder_kernel<<<dim3(NS_ / BM, YD_ / BN), 256, dec_smem>>>(
        Y, Wd_mu, bd_mu, Wd_sig, bd_sig);
    finalize_kernel<<<1, 1>>>((float*)d_out);
}

// round 3
// speedup vs baseline: 2.9942x; 1.3642x over previous
#include <cuda_runtime.h>
#include <cuda_bf16.h>
#include <cstdint>

// Problem constants (fixed by setup_inputs)
#define N_   8192
#define YD_  512
#define XD_  64
#define K_   16
#define S_   10
#define NS_  (N_*S_)   // 81920
#define LOG2PI 1.8378770664093453

// ---- scratch (device globals; no runtime allocation) ----
__device__ float g_enc_mu[N_*XD_];
__device__ float g_enc_sig[N_*XD_];
__device__ __nv_bfloat16 g_xh[NS_*XD_];
__device__ double g_acc[4];   // 0: loss1 partial, 1: loss2+3+4 partial, 2: loss5

__global__ void init_acc_kernel() {
    if (threadIdx.x < 4) g_acc[threadIdx.x] = 0.0;
}

__device__ __forceinline__ float softplus_f(float v) {
    return fmaxf(v, 0.0f) + log1pf(__expf(-fabsf(v)));
}
// fast softplus for the big loss1 epilogue (error ~1e-7 absolute, fine)
__device__ __forceinline__ float softplus_fast(float v) {
    return fmaxf(v, 0.0f) + __logf(1.0f + __expf(-fabsf(v)));
}

__device__ __forceinline__ void ldsm_x4(uint32_t* r, uint32_t addr) {
    asm volatile("ldmatrix.sync.aligned.m8n8.x4.shared.b16 {%0,%1,%2,%3}, [%4];"
        : "=r"(r[0]), "=r"(r[1]), "=r"(r[2]), "=r"(r[3]) : "r"(addr));
}
__device__ __forceinline__ void ldsm_x4_t(uint32_t* r, uint32_t addr) {
    asm volatile("ldmatrix.sync.aligned.m8n8.x4.trans.shared.b16 {%0,%1,%2,%3}, [%4];"
        : "=r"(r[0]), "=r"(r[1]), "=r"(r[2]), "=r"(r[3]) : "r"(addr));
}
#define MMA_BF16(C, A, B0, B1)                                          \
    asm volatile(                                                       \
        "mma.sync.aligned.m16n8k16.row.col.f32.bf16.bf16.f32 "          \
        "{%0,%1,%2,%3}, {%4,%5,%6,%7}, {%8,%9}, {%0,%1,%2,%3};"         \
        : "+f"(C[0]), "+f"(C[1]), "+f"(C[2]), "+f"(C[3])                \
        : "r"(A[0]), "r"(A[1]), "r"(A[2]), "r"(A[3]), "r"(B0), "r"(B1))

// ============================================================
// Kernel 1: encoder GEMM.  C[8192,128] = Y @ [We_mu | We_sig]
// ============================================================
__global__ void __launch_bounds__(256) encoder_kernel(
    const float* __restrict__ Y,
    const float* __restrict__ We_mu, const float* __restrict__ be_mu,
    const float* __restrict__ We_sig, const float* __restrict__ be_sig)
{
    __shared__ float As[32][65];
    __shared__ float Bs[32][128];
    int tid = threadIdx.x;
    int ty = tid >> 4, tx = tid & 15;
    int row0 = blockIdx.x * 64;

    float acc[4][8];
    #pragma unroll
    for (int i = 0; i < 4; i++)
        #pragma unroll
        for (int j = 0; j < 8; j++) acc[i][j] = 0.0f;

    for (int k0 = 0; k0 < YD_; k0 += 32) {
        #pragma unroll
        for (int it = 0; it < 8; it++) {
            int lin = it * 256 + tid;
            int r = lin >> 5, k = lin & 31;
            As[k][r] = Y[(row0 + r) * YD_ + k0 + k];
        }
        #pragma unroll
        for (int it = 0; it < 16; it++) {
            int lin = it * 256 + tid;
            int k = lin >> 7, c = lin & 127;
            Bs[k][c] = (c < 64) ? We_mu[(k0 + k) * XD_ + c]
                                : We_sig[(k0 + k) * XD_ + (c - 64)];
        }
        __syncthreads();
        #pragma unroll
        for (int k = 0; k < 32; k++) {
            float a[4], b[8];
            #pragma unroll
            for (int i = 0; i < 4; i++) a[i] = As[k][ty + 16 * i];
            #pragma unroll
            for (int j = 0; j < 8; j++) b[j] = Bs[k][tx + 16 * j];
            #pragma unroll
            for (int i = 0; i < 4; i++)
                #pragma unroll
                for (int j = 0; j < 8; j++)
                    acc[i][j] = fmaf(a[i], b[j], acc[i][j]);
        }
        __syncthreads();
    }
    #pragma unroll
    for (int i = 0; i < 4; i++) {
        int row = row0 + ty + 16 * i;
        #pragma unroll
        for (int j = 0; j < 8; j++) {
            int c = tx + 16 * j;
            if (c < 64) {
                g_enc_mu[row * XD_ + c] = acc[i][j] + be_mu[c];
            } else {
                int cc = c - 64;
                g_enc_sig[row * XD_ + cc] =
                    softplus_f(acc[i][j] + be_sig[cc]) + 1e-3f;
            }
        }
    }
}

// ============================================================
// Kernel 2: per-n fused GMM responsibilities + gumbel-softmax mixtures
// + x_samp (bf16 out) + losses 2,3,4,5. One 64-thread block per n.
// ============================================================
__global__ void __launch_bounds__(64) mixture_kernel(
    const float* __restrict__ phi_mus, const float* __restrict__ phi_sigs,
    const float* __restrict__ phi_logits,
    const float* __restrict__ theta_mus, const float* __restrict__ theta_sigs,
    const float* __restrict__ theta_logits,
    const float* __restrict__ u_noise, const float* __restrict__ eps_noise,
    const float* __restrict__ temperature)
{
    int n = blockIdx.x;
    int tid = threadIdx.x;   // 0..63, thread = dimension d
    __shared__ float s_pmu[16 * 65], s_psg[16 * 65];
    __shared__ float s_tmu[16 * 65], s_tsg[16 * 65];
    __shared__ float s_mut[16 * 65], s_sgt[16 * 65];
    __shared__ float em[64], es[64];
    __shared__ float lpi[16], lth[16];
    __shared__ float zl[16], zlp[16];
    __shared__ float s_z[S_][17];
    __shared__ float sdt[S_];
    __shared__ float red[16][4];
    __shared__ float wred[2];
    __shared__ float sl5;

    int d = tid;
    float emd = g_enc_mu[n * XD_ + d];
    float esd = g_enc_sig[n * XD_ + d];
    em[d] = emd; es[d] = esd;
    float iesd = 1.0f / esd;

    #pragma unroll
    for (int k = 0; k < 16; k++) {
        s_pmu[k * 65 + d] = phi_mus[k * XD_ + d];
        s_psg[k * 65 + d] = phi_sigs[k * XD_ + d];
        s_tmu[k * 65 + d] = theta_mus[k * XD_ + d];
        s_tsg[k * 65 + d] = theta_sigs[k * XD_ + d];
    }
    if (tid == 0) {
        float m = -1e30f;
        for (int k = 0; k < 16; k++) m = fmaxf(m, phi_logits[k]);
        float sm = 0.0f;
        for (int k = 0; k < 16; k++) sm += __expf(phi_logits[k] - m);
        float lse = m + __logf(sm);
        for (int k = 0; k < 16; k++) lpi[k] = phi_logits[k] - lse;
    }
    if (tid == 1) {
        float m = -1e30f;
        for (int k = 0; k < 16; k++) m = fmaxf(m, theta_logits[k]);
        float sm = 0.0f;
        for (int k = 0; k < 16; k++) sm += __expf(theta_logits[k] - m);
        float lse = m + __logf(sm);
        for (int k = 0; k < 16; k++) lth[k] = theta_logits[k] - lse;
    }
    __syncthreads();

    // z_logits: 16 k x 4 groups of 16 dims
    {
        int k = tid >> 2, g = tid & 3;
        float a = 0.0f;
        #pragma unroll
        for (int i = 0; i < 16; i++) {
            int dd = g * 16 + i;
            float std = es[dd] + s_psg[k * 65 + dd];
            float t = __fdividef(em[dd] - s_pmu[k * 65 + dd], std);
            a += 0.5f * t * t + __logf(std);
        }
        red[k][g] = a;
    }
    __syncthreads();
    if (tid < 16) {
        int k = tid;
        zl[k] = lpi[k] - 0.5f * 64.0f * (float)LOG2PI
              - (red[k][0] + red[k][1] + red[k][2] + red[k][3]);
    }
    __syncthreads();

    if (tid == 0) {
        float m = -1e30f;
        for (int k = 0; k < 16; k++) m = fmaxf(m, zl[k]);
        float sm = 0.0f;
        for (int k = 0; k < 16; k++) sm += __expf(zl[k] - m);
        float lse = m + __logf(sm);
        for (int k = 0; k < 16; k++) zlp[k] = zl[k] - lse;
        float s2 = 0.0f;
        for (int k = 0; k < 16; k++) s2 += __expf(zlp[k]);
        sl5 = __logf(s2);
    }

    // per-cluster posterior mu_t / Sig_t
    #pragma unroll
    for (int k = 0; k < 16; k++) {
        float ig = 1.0f / s_psg[k * 65 + d];
        float st = 1.0f / (iesd + ig);
        s_sgt[k * 65 + d] = st;
        s_mut[k * 65 + d] = st * (iesd * emd + ig * s_pmu[k * 65 + d]);
    }
    __syncthreads();

    // parallel gumbel-softmax: one thread per sample s
    float invT = 1.0f / temperature[0];
    if (tid < S_) {
        int s = tid;
        const float* urow = u_noise + n * (S_ * K_) + s * K_;
        float v[16];
        float m = -1e30f;
        #pragma unroll
        for (int k = 0; k < 16; k++) {
            float gg = -__logf(-__logf(urow[k]));
            v[k] = (zlp[k] + gg) * invT;
            m = fmaxf(m, v[k]);
        }
        float sm = 0.0f;
        #pragma unroll
        for (int k = 0; k < 16; k++) { v[k] = __expf(v[k] - m); sm += v[k]; }
        float inv = 1.0f / sm;
        float dt = 0.0f;
        #pragma unroll
        for (int k = 0; k < 16; k++) {
            float z = v[k] * inv;
            s_z[s][k] = z;
            dt = fmaf(z, lth[k] - zlp[k], dt);
        }
        sdt[s] = dt;
    }
    __syncthreads();

    // mixture accumulation, k-outer (table reads hoisted out of s-loop)
    float ms[S_], ssg[S_], tm[S_], tsg[S_], pm[S_], psg[S_];
    #pragma unroll
    for (int s = 0; s < S_; s++) {
        ms[s] = 0.f; ssg[s] = 0.f; tm[s] = 0.f;
        tsg[s] = 0.f; pm[s] = 0.f; psg[s] = 0.f;
    }
    #pragma unroll
    for (int k = 0; k < 16; k++) {
        float mut = s_mut[k * 65 + d];
        float sgt = s_sgt[k * 65 + d];
        float tmu = s_tmu[k * 65 + d];
        float tsig = s_tsg[k * 65 + d];
        float pmu = s_pmu[k * 65 + d];
        float psig = s_psg[k * 65 + d];
        #pragma unroll
        for (int s = 0; s < S_; s++) {
            float z = s_z[s][k];
            ms[s]  = fmaf(z, mut, ms[s]);
            ssg[s] = fmaf(z, sgt, ssg[s]);
            tm[s]  = fmaf(z, tmu, tm[s]);
            tsg[s] = fmaf(z, tsig, tsg[s]);
            pm[s]  = fmaf(z, pmu, pm[s]);
            psg[s] = fmaf(z, psig, psg[s]);
        }
    }

    float lacc = 0.0f;
    #pragma unroll
    for (int s = 0; s < S_; s++) {
        int row = n * S_ + s;
        float x = fmaf(sqrtf(ssg[s]), eps_noise[row * XD_ + d], ms[s]);
        g_xh[row * XD_ + d] = __float2bfloat16_rn(x);
        float te = (x - emd) * iesd;
        float tt = __fdividef(x - tm[s], tsg[s]);
        float tp = __fdividef(x - pm[s], psg[s]);
        lacc += 0.5f * (te * te - tt * tt + tp * tp)
              - __logf(tsg[s]) + __logf(psg[s]);
    }
    lacc += (float)S_ * __logf(esd);   // He term, constant over s

    #pragma unroll
    for (int o = 16; o > 0; o >>= 1)
        lacc += __shfl_down_sync(0xffffffffu, lacc, o);
    if ((tid & 31) == 0) wred[tid >> 5] = lacc;
    __syncthreads();
    if (tid == 0) {
        float dts = 0.0f;
        #pragma unroll
        for (int s = 0; s < S_; s++) dts += sdt[s];
        double tot = (double)(wred[0] + wred[1]) + (double)dts;
        atomicAdd(&g_acc[1], tot);
        atomicAdd(&g_acc[2], (double)sl5);
    }
}

// ============================================================
// Kernel 3: bf16 tensor-core decoder GEMMs (m16n8k16 + ldmatrix)
// fused with loss1.  Block tile 128(M) x 64(N), full K=64 in smem,
// 8 warps (4M x 2N).  mu_y / sig_y never hit global memory.
// ============================================================
#define BM 128
#define BN 64
#define SA 72   // bf16 row stride for A  (144B, conflict-free for ldmatrix)
#define SB 72   // bf16 row stride for B
#define DEC_SMEM_BYTES ((BM*SA + 2*64*SB) * 2 + 2 * BN * 4)

__global__ void __launch_bounds__(256) decoder_kernel(
    const float* __restrict__ Y,
    const float* __restrict__ Wd_mu, const float* __restrict__ bd_mu,
    const float* __restrict__ Wd_sig, const float* __restrict__ bd_sig)
{
    extern __shared__ __align__(16) char smem_raw[];
    __nv_bfloat16* sA  = (__nv_bfloat16*)smem_raw;   // [BM][SA]
    __nv_bfloat16* sBm = sA + BM * SA;               // [64][SB]
    __nv_bfloat16* sBs = sBm + 64 * SB;              // [64][SB]
    float* sbm = (float*)(sBs + 64 * SB);            // [BN]
    float* sbs = sbm + BN;                           // [BN]
    __shared__ float warp_red[8];

    int tid = threadIdx.x;
    int warp = tid >> 5, lane = tid & 31;
    int row0 = blockIdx.x * BM;        // NS-row offset
    int col0 = blockIdx.y * BN;        // Yd-col offset

    // --- stage A (bf16 g_xh tile, vectorized 16B copies) ---
    const __nv_bfloat16* gx = g_xh + (size_t)row0 * XD_;
    #pragma unroll
    for (int i = tid; i < BM * 8; i += 256) {
        int r = i >> 3, c8 = (i & 7) * 8;
        uint4 v = *(const uint4*)(gx + r * XD_ + c8);
        *(uint4*)(sA + r * SA + c8) = v;
    }
    // --- stage B (fp32 weights -> bf16, [k][n]) ---
    #pragma unroll
    for (int i = tid; i < 64 * 16; i += 256) {
        int k = i >> 4, c4 = (i & 15) * 4;
        float4 vm = *(const float4*)(Wd_mu + k * YD_ + col0 + c4);
        float4 vs = *(const float4*)(Wd_sig + k * YD_ + col0 + c4);
        *(__nv_bfloat162*)(sBm + k * SB + c4)     = __floats2bfloat162_rn(vm.x, vm.y);
        *(__nv_bfloat162*)(sBm + k * SB + c4 + 2) = __floats2bfloat162_rn(vm.z, vm.w);
        *(__nv_bfloat162*)(sBs + k * SB + c4)     = __floats2bfloat162_rn(vs.x, vs.y);
        *(__nv_bfloat162*)(sBs + k * SB + c4 + 2) = __floats2bfloat162_rn(vs.z, vs.w);
    }
    if (tid < BN) {
        sbm[tid] = bd_mu[col0 + tid];
        sbs[tid] = bd_sig[col0 + tid];
    }
    __syncthreads();

    int wm = warp & 3;          // 4 M-warps (32 rows each)
    int wn = warp >> 2;         // 2 N-warps (32 cols each)
    int mBase = wm * 32;
    int nBase = wn * 32;
    int g = lane >> 2, tg = lane & 3;

    // per-lane ldmatrix source addresses
    int mi = lane >> 3;         // matrix index 0..3
    int ri = lane & 7;          // row within matrix
    uint32_t aBase  = (uint32_t)__cvta_generic_to_shared(sA);
    uint32_t bmBase = (uint32_t)__cvta_generic_to_shared(sBm);
    uint32_t bsBase = (uint32_t)__cvta_generic_to_shared(sBs);
    // A: lanes 0-7:(m0-7,k0) 8-15:(m8-15,k0) 16-23:(m0-7,k8) 24-31:(m8-15,k8)
    uint32_t aAddr[2];
    #pragma unroll
    for (int mt = 0; mt < 2; mt++)
        aAddr[mt] = aBase +
            (((mBase + mt * 16 + (mi & 1) * 8 + ri) * SA) + (mi >> 1) * 8) * 2;
    // B: lanes 0-7:(k0-7,n0) 8-15:(k8-15,n0) 16-23:(k0-7,n8) 24-31:(k8-15,n8)
    uint32_t bmAddr[2], bsAddr[2];
    #pragma unroll
    for (int p = 0; p < 2; p++) {
        uint32_t off = (((mi & 1) * 8 + ri) * SB + nBase + p * 16 + (mi >> 1) * 8) * 2;
        bmAddr[p] = bmBase + off;
        bsAddr[p] = bsBase + off;
    }

    float cm[2][4][4], cs[2][4][4];
    #pragma unroll
    for (int mt = 0; mt < 2; mt++)
        #pragma unroll
        for (int nt = 0; nt < 4; nt++)
            #pragma unroll
            for (int r = 0; r < 4; r++) { cm[mt][nt][r] = 0.f; cs[mt][nt][r] = 0.f; }

    #pragma unroll
    for (int ks = 0; ks < 4; ks++) {            // k16 steps over K=64
        uint32_t a[2][4];
        ldsm_x4(a[0], aAddr[0] + ks * 32);      // +16 bf16 = 32B along row
        ldsm_x4(a[1], aAddr[1] + ks * 32);
        uint32_t bm[2][4], bs[2][4];
        #pragma unroll
        for (int p = 0; p < 2; p++) {
            ldsm_x4_t(bm[p], bmAddr[p] + ks * (16 * SB * 2));
            ldsm_x4_t(bs[p], bsAddr[p] + ks * (16 * SB * 2));
        }
        #pragma unroll
        for (int nt = 0; nt < 4; nt++) {
            int p = nt >> 1, sel = (nt & 1) * 2;
            #pragma unroll
            for (int mt = 0; mt < 2; mt++) {
                MMA_BF16(cm[mt][nt], a[mt], bm[p][sel], bm[p][sel + 1]);
                MMA_BF16(cs[mt][nt], a[mt], bs[p][sel], bs[p][sel + 1]);
            }
        }
    }

    // --- fused loss1 epilogue (batched log over 8-element products) ---
    float part = 0.0f;
    #pragma unroll
    for (int mt = 0; mt < 2; mt++) {
        #pragma unroll
        for (int half = 0; half < 2; half++) {
            int row = row0 + mBase + mt * 16 + g + half * 8;
            int n = row / S_;
            const float* yrow = Y + n * YD_ + col0;
            float prod = 1.0f;
            #pragma unroll
            for (int nt = 0; nt < 4; nt++) {
                #pragma unroll
                for (int p = 0; p < 2; p++) {
                    int r = half * 2 + p;
                    int cl = nBase + nt * 8 + tg * 2 + p;
                    float mu = cm[mt][nt][r] + sbm[cl];
                    float sg = softplus_fast(cs[mt][nt][r] + sbs[cl]) + 1e-3f;
                    float t = __fdividef(yrow[cl] - mu, sg);
                    part -= 0.5f * t * t;
                    prod *= sg;
                }
            }
            part -= __logf(prod);
        }
    }
    #pragma unroll
    for (int o = 16; o > 0; o >>= 1)
        part += __shfl_down_sync(0xffffffffu, part, o);
    if (lane == 0) warp_red[warp] = part;
    __syncthreads();
    if (tid == 0) {
        float tot = 0.0f;
        #pragma unroll
        for (int w = 0; w < 8; w++) tot += warp_red[w];
        atomicAdd(&g_acc[0], (double)tot);
    }
}

// ============================================================
// Kernel 4: finalize.
// ============================================================
__global__ void finalize_kernel(float* out) {
    double NSd = (double)NS_;
    double L1   = g_acc[0] - 0.5 * (double)YD_ * LOG2PI * NSd;
    double L234 = g_acc[1] + 0.5 * (double)XD_ * LOG2PI * NSd;
    double tot = (L1 + L234) / (double)S_ + g_acc[2];
    out[0] = (float)(-tot);
}

extern "C" void kernel_launch(void* const* d_in, const int* in_sizes, int n_in,
                              void* d_out, int out_size)
{
    const float* Y            = (const float*)d_in[0];
    const float* We_mu        = (const float*)d_in[1];
    const float* be_mu        = (const float*)d_in[2];
    const float* We_sig       = (const float*)d_in[3];
    const float* be_sig       = (const float*)d_in[4];
    const float* Wd_mu        = (const float*)d_in[5];
    const float* bd_mu        = (const float*)d_in[6];
    const float* Wd_sig       = (const float*)d_in[7];
    const float* bd_sig       = (const float*)d_in[8];
    const float* phi_mus      = (const float*)d_in[9];
    const float* phi_sigs     = (const float*)d_in[10];
    const float* phi_logits   = (const float*)d_in[11];
    const float* theta_mus    = (const float*)d_in[12];
    const float* theta_sigs   = (const float*)d_in[13];
    const float* theta_logits = (const float*)d_in[14];
    const float* u_noise      = (const float*)d_in[15];
    const float* eps_noise    = (const float*)d_in[16];
    const float* temperature  = (const float*)d_in[17];

    cudaFuncSetAttribute(decoder_kernel,
                         cudaFuncAttributeMaxDynamicSharedMemorySize,
                         DEC_SMEM_BYTES);

    init_acc_kernel<<<1, 32>>>();
    encoder_kernel<<<N_ / 64, 256>>>(Y, We_mu, be_mu, We_sig, be_sig);
    mixture_kernel<<<N_, 64>>>(phi_mus, phi_sigs, phi_logits,
                               theta_mus, theta_sigs, theta_logits,
                               u_noise, eps_noise, temperature);
    decoder_kernel<<<dim3(NS_ / BM, YD_ / BN), 256, DEC_SMEM_BYTES>>>(
        Y, Wd_mu, bd_mu, Wd_sig, bd_sig);
    finalize_kernel<<<1, 1>>>((float*)d_out);
}

// round 4
// speedup vs baseline: 3.4007x; 1.1358x over previous
#include <cuda_runtime.h>
#include <cuda_bf16.h>
#include <cstdint>

// Problem constants (fixed by setup_inputs)
#define N_   8192
#define YD_  512
#define XD_  64
#define K_   16
#define S_   10
#define NS_  (N_*S_)   // 81920
#define LOG2PI 1.8378770664093453

// ---- scratch (device globals; no runtime allocation) ----
__device__ float g_enc_mu[N_*XD_];
__device__ float g_enc_sig[N_*XD_];
__device__ __nv_bfloat16 g_xh[NS_*XD_];
__device__ double g_acc[4];   // 0: loss1, 1: loss2+3+4, 2: loss5

__device__ __forceinline__ float softplus_f(float v) {
    return fmaxf(v, 0.0f) + log1pf(__expf(-fabsf(v)));
}
__device__ __forceinline__ float softplus_fast(float v) {
    return fmaxf(v, 0.0f) + __logf(1.0f + __expf(-fabsf(v)));
}

__device__ __forceinline__ void ldsm_x4(uint32_t* r, uint32_t addr) {
    asm volatile("ldmatrix.sync.aligned.m8n8.x4.shared.b16 {%0,%1,%2,%3}, [%4];"
        : "=r"(r[0]), "=r"(r[1]), "=r"(r[2]), "=r"(r[3]) : "r"(addr));
}
__device__ __forceinline__ void ldsm_x4_t(uint32_t* r, uint32_t addr) {
    asm volatile("ldmatrix.sync.aligned.m8n8.x4.trans.shared.b16 {%0,%1,%2,%3}, [%4];"
        : "=r"(r[0]), "=r"(r[1]), "=r"(r[2]), "=r"(r[3]) : "r"(addr));
}
#define MMA_BF16(C, A, B0, B1)                                          \
    asm volatile(                                                       \
        "mma.sync.aligned.m16n8k16.row.col.f32.bf16.bf16.f32 "          \
        "{%0,%1,%2,%3}, {%4,%5,%6,%7}, {%8,%9}, {%0,%1,%2,%3};"         \
        : "+f"(C[0]), "+f"(C[1]), "+f"(C[2]), "+f"(C[3])                \
        : "r"(A[0]), "r"(A[1]), "r"(A[2]), "r"(A[3]), "r"(B0), "r"(B1))

// ============================================================
// Kernel 1: bf16 tensor-core encoder GEMM.
// C[8192,128] = Y[8192,512] @ [We_mu | We_sig].
// BM=64, BN=128, 256 thr, 8 warps (2M x 4N), warp tile 32x32.
// Also zeroes g_acc (block 0).
// ============================================================
#define ESA 72
#define ESB 136

__global__ void __launch_bounds__(256) encoder_kernel(
    const float* __restrict__ Y,
    const float* __restrict__ We_mu, const float* __restrict__ be_mu,
    const float* __restrict__ We_sig, const float* __restrict__ be_sig)
{
    __shared__ __align__(16) __nv_bfloat16 sA[64 * ESA];
    __shared__ __align__(16) __nv_bfloat16 sB[64 * ESB];

    int tid = threadIdx.x;
    int warp = tid >> 5, lane = tid & 31;
    int row0 = blockIdx.x * 64;

    if (blockIdx.x == 0 && tid < 4) g_acc[tid] = 0.0;

    int mBase = (warp & 1) * 32;
    int nBase = (warp >> 1) * 32;
    int g = lane >> 2, tg = lane & 3;
    int mi = lane >> 3, ri = lane & 7;

    uint32_t aBase = (uint32_t)__cvta_generic_to_shared(sA);
    uint32_t bBase = (uint32_t)__cvta_generic_to_shared(sB);
    uint32_t aAddr[2];
    #pragma unroll
    for (int mt = 0; mt < 2; mt++)
        aAddr[mt] = aBase +
            (((mBase + mt * 16 + (mi & 1) * 8 + ri) * ESA) + (mi >> 1) * 8) * 2;
    uint32_t bAddr[2];
    #pragma unroll
    for (int p = 0; p < 2; p++)
        bAddr[p] = bBase +
            ((((mi & 1) * 8 + ri) * ESB) + nBase + p * 16 + (mi >> 1) * 8) * 2;

    float acc[2][4][4];
    #pragma unroll
    for (int mt = 0; mt < 2; mt++)
        #pragma unroll
        for (int nt = 0; nt < 4; nt++)
            #pragma unroll
            for (int r = 0; r < 4; r++) acc[mt][nt][r] = 0.f;

    for (int kc = 0; kc < 8; kc++) {
        int k0 = kc * 64;
        // stage A: 64 rows x 64 k (fp32 -> bf16)
        #pragma unroll
        for (int i = tid; i < 64 * 16; i += 256) {
            int r = i >> 4, c4 = (i & 15) * 4;
            float4 v = *(const float4*)(Y + (size_t)(row0 + r) * YD_ + k0 + c4);
            *(__nv_bfloat162*)(sA + r * ESA + c4)     = __floats2bfloat162_rn(v.x, v.y);
            *(__nv_bfloat162*)(sA + r * ESA + c4 + 2) = __floats2bfloat162_rn(v.z, v.w);
        }
        // stage B: 64 k-rows x 128 cols ([We_mu | We_sig])
        #pragma unroll
        for (int i = tid; i < 64 * 32; i += 256) {
            int k = i >> 5, c4 = (i & 31) * 4;
            const float* src = (c4 < 64) ? We_mu + (k0 + k) * XD_ + c4
                                         : We_sig + (k0 + k) * XD_ + (c4 - 64);
            float4 v = *(const float4*)src;
            *(__nv_bfloat162*)(sB + k * ESB + c4)     = __floats2bfloat162_rn(v.x, v.y);
            *(__nv_bfloat162*)(sB + k * ESB + c4 + 2) = __floats2bfloat162_rn(v.z, v.w);
        }
        __syncthreads();
        #pragma unroll
        for (int ks = 0; ks < 4; ks++) {
            uint32_t a[2][4];
            ldsm_x4(a[0], aAddr[0] + ks * 32);
            ldsm_x4(a[1], aAddr[1] + ks * 32);
            uint32_t b[2][4];
            ldsm_x4_t(b[0], bAddr[0] + ks * (16 * ESB * 2));
            ldsm_x4_t(b[1], bAddr[1] + ks * (16 * ESB * 2));
            #pragma unroll
            for (int nt = 0; nt < 4; nt++) {
                int p = nt >> 1, sel = (nt & 1) * 2;
                MMA_BF16(acc[0][nt], a[0], b[p][sel], b[p][sel + 1]);
                MMA_BF16(acc[1][nt], a[1], b[p][sel], b[p][sel + 1]);
            }
        }
        __syncthreads();
    }
    // epilogue: cols<64 -> enc_mu, cols>=64 -> softplus -> enc_sig
    #pragma unroll
    for (int mt = 0; mt < 2; mt++) {
        #pragma unroll
        for (int half = 0; half < 2; half++) {
            int row = row0 + mBase + mt * 16 + g + half * 8;
            #pragma unroll
            for (int nt = 0; nt < 4; nt++) {
                #pragma unroll
                for (int p = 0; p < 2; p++) {
                    int cl = nBase + nt * 8 + tg * 2 + p;
                    float c = acc[mt][nt][half * 2 + p];
                    if (cl < 64) {
                        g_enc_mu[row * XD_ + cl] = c + be_mu[cl];
                    } else {
                        int cc = cl - 64;
                        g_enc_sig[row * XD_ + cc] =
                            softplus_f(c + be_sig[cc]) + 1e-3f;
                    }
                }
            }
        }
    }
}

// ============================================================
// Kernel 2: fused GMM responsibilities + gumbel-softmax mixtures
// + x_samp (bf16) + losses 2,3,4,5.  Two n per 128-thread block.
// ============================================================
__global__ void __launch_bounds__(128) mixture_kernel(
    const float* __restrict__ phi_mus, const float* __restrict__ phi_sigs,
    const float* __restrict__ phi_logits,
    const float* __restrict__ theta_mus, const float* __restrict__ theta_sigs,
    const float* __restrict__ theta_logits,
    const float* __restrict__ u_noise, const float* __restrict__ eps_noise,
    const float* __restrict__ temperature)
{
    int tid = threadIdx.x;
    int sub = tid >> 6;         // 0/1: which n
    int d = tid & 63;
    int n = blockIdx.x * 2 + sub;

    __shared__ float s_pmu[16 * 65], s_psg[16 * 65];
    __shared__ float s_tmu[16 * 65], s_tsg[16 * 65];
    __shared__ float em[2][64], es[2][64];
    __shared__ float lpi[16], lth[16];
    __shared__ float zl[2][16], zlp[2][16];
    __shared__ float s_z[2][S_][17];
    __shared__ float sdt[2][S_];
    __shared__ float red[2][16][4];
    __shared__ float wred[2][2];
    __shared__ float sl5[2];

    // shared parameter tables (both subs cooperate)
    for (int k = sub; k < 16; k += 2) {
        s_pmu[k * 65 + d] = phi_mus[k * XD_ + d];
        s_psg[k * 65 + d] = phi_sigs[k * XD_ + d];
        s_tmu[k * 65 + d] = theta_mus[k * XD_ + d];
        s_tsg[k * 65 + d] = theta_sigs[k * XD_ + d];
    }
    float emd = g_enc_mu[n * XD_ + d];
    float esd = g_enc_sig[n * XD_ + d];
    em[sub][d] = emd; es[sub][d] = esd;
    float iesd = 1.0f / esd;

    if (tid == 0) {
        float m = -1e30f;
        for (int k = 0; k < 16; k++) m = fmaxf(m, phi_logits[k]);
        float sm = 0.0f;
        for (int k = 0; k < 16; k++) sm += __expf(phi_logits[k] - m);
        float lse = m + __logf(sm);
        for (int k = 0; k < 16; k++) lpi[k] = phi_logits[k] - lse;
    }
    if (tid == 1) {
        float m = -1e30f;
        for (int k = 0; k < 16; k++) m = fmaxf(m, theta_logits[k]);
        float sm = 0.0f;
        for (int k = 0; k < 16; k++) sm += __expf(theta_logits[k] - m);
        float lse = m + __logf(sm);
        for (int k = 0; k < 16; k++) lth[k] = theta_logits[k] - lse;
    }
    __syncthreads();

    // z_logits: per sub, thread (k = d>>2, g4 = d&3) reduces 16 dims
    {
        int k = d >> 2, g4 = d & 3;
        float a = 0.0f, prod = 1.0f;
        #pragma unroll
        for (int i = 0; i < 16; i++) {
            int dd = g4 * 16 + i;
            float std = es[sub][dd] + s_psg[k * 65 + dd];
            float t = __fdividef(em[sub][dd] - s_pmu[k * 65 + dd], std);
            a += 0.5f * t * t;
            prod *= std;
        }
        red[sub][k][g4] = a + __logf(prod);
    }
    __syncthreads();
    if (d < 16)
        zl[sub][d] = lpi[d] - 0.5f * 64.0f * (float)LOG2PI
            - (red[sub][d][0] + red[sub][d][1] + red[sub][d][2] + red[sub][d][3]);
    __syncthreads();
    if (d == 0) {
        float m = -1e30f;
        for (int k = 0; k < 16; k++) m = fmaxf(m, zl[sub][k]);
        float sm = 0.0f;
        for (int k = 0; k < 16; k++) sm += __expf(zl[sub][k] - m);
        float lse = m + __logf(sm);
        for (int k = 0; k < 16; k++) zlp[sub][k] = zl[sub][k] - lse;
        float s2 = 0.0f;
        for (int k = 0; k < 16; k++) s2 += __expf(zlp[sub][k]);
        sl5[sub] = __logf(s2);
    }
    __syncthreads();

    // parallel gumbel-softmax: threads d<10 of each sub handle one s
    float invT = 1.0f / temperature[0];
    if (d < S_) {
        int s = d;
        const float* urow = u_noise + (size_t)n * (S_ * K_) + s * K_;
        float v[16];
        float m = -1e30f;
        #pragma unroll
        for (int k = 0; k < 16; k++) {
            float gg = -__logf(-__logf(urow[k]));
            v[k] = (zlp[sub][k] + gg) * invT;
            m = fmaxf(m, v[k]);
        }
        float sm = 0.0f;
        #pragma unroll
        for (int k = 0; k < 16; k++) { v[k] = __expf(v[k] - m); sm += v[k]; }
        float inv = 1.0f / sm;
        float dt = 0.0f;
        #pragma unroll
        for (int k = 0; k < 16; k++) {
            float z = v[k] * inv;
            s_z[sub][s][k] = z;
            dt = fmaf(z, lth[k] - zlp[sub][k], dt);
        }
        sdt[sub][s] = dt;
    }
    __syncthreads();

    // mixture accumulation, k-outer; posterior computed inline
    float ms[S_], ssg[S_], tm[S_], tsg[S_], pm[S_], psg[S_];
    #pragma unroll
    for (int s = 0; s < S_; s++) {
        ms[s] = 0.f; ssg[s] = 0.f; tm[s] = 0.f;
        tsg[s] = 0.f; pm[s] = 0.f; psg[s] = 0.f;
    }
    #pragma unroll
    for (int k = 0; k < 16; k++) {
        float pmu  = s_pmu[k * 65 + d];
        float psig = s_psg[k * 65 + d];
        float tmu  = s_tmu[k * 65 + d];
        float tsig = s_tsg[k * 65 + d];
        float ig = __fdividef(1.0f, psig);
        float st = __fdividef(1.0f, iesd + ig);
        float mut = st * fmaf(ig, pmu, iesd * emd);
        #pragma unroll
        for (int s = 0; s < S_; s++) {
            float z = s_z[sub][s][k];
            ms[s]  = fmaf(z, mut, ms[s]);
            ssg[s] = fmaf(z, st, ssg[s]);
            tm[s]  = fmaf(z, tmu, tm[s]);
            tsg[s] = fmaf(z, tsig, tsg[s]);
            pm[s]  = fmaf(z, pmu, pm[s]);
            psg[s] = fmaf(z, psig, psg[s]);
        }
    }

    float lacc = 0.0f;
    float lp = 1.0f;   // product of psg/tsg over s
    #pragma unroll
    for (int s = 0; s < S_; s++) {
        int row = n * S_ + s;
        float x = fmaf(sqrtf(ssg[s]), eps_noise[(size_t)row * XD_ + d], ms[s]);
        g_xh[(size_t)row * XD_ + d] = __float2bfloat16_rn(x);
        float te = (x - emd) * iesd;
        float rt = __fdividef(1.0f, tsg[s]);
        float rp = __fdividef(1.0f, psg[s]);
        float tt = (x - tm[s]) * rt;
        float tp = (x - pm[s]) * rp;
        lacc += 0.5f * (te * te - tt * tt + tp * tp);
        lp *= psg[s] * rt;
    }
    lacc += __logf(lp) + (float)S_ * __logf(esd);

    #pragma unroll
    for (int o = 16; o > 0; o >>= 1)
        lacc += __shfl_down_sync(0xffffffffu, lacc, o);
    if ((tid & 31) == 0) wred[sub][(tid >> 5) & 1] = lacc;
    __syncthreads();
    if (d == 0) {
        float dts = 0.0f;
        #pragma unroll
        for (int s = 0; s < S_; s++) dts += sdt[sub][s];
        double tot = (double)(wred[sub][0] + wred[sub][1]) + (double)dts;
        atomicAdd(&g_acc[1], tot);
        atomicAdd(&g_acc[2], (double)sl5[sub]);
    }
}

// ============================================================
// Kernel 3: bf16 decoder GEMMs fused with loss1.
// BM=64, BN=64, 256 thr, 8 warps (4M x 2N), warp tile 16x32.
// ============================================================
#define SA 72
#define SB 72

__global__ void __launch_bounds__(256, 3) decoder_kernel(
    const float* __restrict__ Y,
    const float* __restrict__ Wd_mu, const float* __restrict__ bd_mu,
    const float* __restrict__ Wd_sig, const float* __restrict__ bd_sig)
{
    __shared__ __align__(16) __nv_bfloat16 sA[64 * SA];
    __shared__ __align__(16) __nv_bfloat16 sBm[64 * SB];
    __shared__ __align__(16) __nv_bfloat16 sBs[64 * SB];
    __shared__ float sbm[64], sbs[64];
    __shared__ float warp_red[8];

    int tid = threadIdx.x;
    int warp = tid >> 5, lane = tid & 31;
    int row0 = blockIdx.x * 64;        // NS-row offset
    int col0 = blockIdx.y * 64;        // Yd-col offset

    // --- stage A (bf16 g_xh tile) ---
    const __nv_bfloat16* gx = g_xh + (size_t)row0 * XD_;
    #pragma unroll
    for (int i = tid; i < 64 * 8; i += 256) {
        int r = i >> 3, c8 = (i & 7) * 8;
        *(uint4*)(sA + r * SA + c8) = *(const uint4*)(gx + r * XD_ + c8);
    }
    // --- stage B (fp32 weights -> bf16) ---
    #pragma unroll
    for (int i = tid; i < 64 * 16; i += 256) {
        int k = i >> 4, c4 = (i & 15) * 4;
        float4 vm = *(const float4*)(Wd_mu + k * YD_ + col0 + c4);
        float4 vs = *(const float4*)(Wd_sig + k * YD_ + col0 + c4);
        *(__nv_bfloat162*)(sBm + k * SB + c4)     = __floats2bfloat162_rn(vm.x, vm.y);
        *(__nv_bfloat162*)(sBm + k * SB + c4 + 2) = __floats2bfloat162_rn(vm.z, vm.w);
        *(__nv_bfloat162*)(sBs + k * SB + c4)     = __floats2bfloat162_rn(vs.x, vs.y);
        *(__nv_bfloat162*)(sBs + k * SB + c4 + 2) = __floats2bfloat162_rn(vs.z, vs.w);
    }
    if (tid < 64) {
        sbm[tid] = bd_mu[col0 + tid];
        sbs[tid] = bd_sig[col0 + tid];
    }
    __syncthreads();

    int mBase = (warp & 3) * 16;       // 4 M-warps x 16 rows
    int nBase = (warp >> 2) * 32;      // 2 N-warps x 32 cols
    int g = lane >> 2, tg = lane & 3;
    int mi = lane >> 3, ri = lane & 7;

    uint32_t aBase  = (uint32_t)__cvta_generic_to_shared(sA);
    uint32_t bmBase = (uint32_t)__cvta_generic_to_shared(sBm);
    uint32_t bsBase = (uint32_t)__cvta_generic_to_shared(sBs);
    uint32_t aAddr = aBase +
        (((mBase + (mi & 1) * 8 + ri) * SA) + (mi >> 1) * 8) * 2;
    uint32_t bmAddr[2], bsAddr[2];
    #pragma unroll
    for (int p = 0; p < 2; p++) {
        uint32_t off = (((mi & 1) * 8 + ri) * SB + nBase + p * 16 + (mi >> 1) * 8) * 2;
        bmAddr[p] = bmBase + off;
        bsAddr[p] = bsBase + off;
    }

    float cm[4][4], cs[4][4];
    #pragma unroll
    for (int nt = 0; nt < 4; nt++)
        #pragma unroll
        for (int r = 0; r < 4; r++) { cm[nt][r] = 0.f; cs[nt][r] = 0.f; }

    #pragma unroll
    for (int ks = 0; ks < 4; ks++) {
        uint32_t a[4];
        ldsm_x4(a, aAddr + ks * 32);
        uint32_t bm[2][4], bs[2][4];
        #pragma unroll
        for (int p = 0; p < 2; p++) {
            ldsm_x4_t(bm[p], bmAddr[p] + ks * (16 * SB * 2));
            ldsm_x4_t(bs[p], bsAddr[p] + ks * (16 * SB * 2));
        }
        #pragma unroll
        for (int nt = 0; nt < 4; nt++) {
            int p = nt >> 1, sel = (nt & 1) * 2;
            MMA_BF16(cm[nt], a, bm[p][sel], bm[p][sel + 1]);
            MMA_BF16(cs[nt], a, bs[p][sel], bs[p][sel + 1]);
        }
    }

    // --- fused loss1 epilogue (batched log over 8-element products) ---
    float part = 0.0f;
    #pragma unroll
    for (int half = 0; half < 2; half++) {
        int row = row0 + mBase + g + half * 8;
        int n = row / S_;
        const float* yrow = Y + (size_t)n * YD_ + col0;
        float prod = 1.0f;
        #pragma unroll
        for (int nt = 0; nt < 4; nt++) {
            #pragma unroll
            for (int p = 0; p < 2; p++) {
                int r = half * 2 + p;
                int cl = nBase + nt * 8 + tg * 2 + p;
                float mu = cm[nt][r] + sbm[cl];
                float sg = softplus_fast(cs[nt][r] + sbs[cl]) + 1e-3f;
                float t = __fdividef(yrow[cl] - mu, sg);
                part -= 0.5f * t * t;
                prod *= sg;
            }
        }
        part -= __logf(prod);
    }
    #pragma unroll
    for (int o = 16; o > 0; o >>= 1)
        part += __shfl_down_sync(0xffffffffu, part, o);
    if (lane == 0) warp_red[warp] = part;
    __syncthreads();
    if (tid == 0) {
        float tot = 0.0f;
        #pragma unroll
        for (int w = 0; w < 8; w++) tot += warp_red[w];
        atomicAdd(&g_acc[0], (double)tot);
    }
}

// ============================================================
// Kernel 4: finalize.
// ============================================================
__global__ void finalize_kernel(float* out) {
    double NSd = (double)NS_;
    double L1   = g_acc[0] - 0.5 * (double)YD_ * LOG2PI * NSd;
    double L234 = g_acc[1] + 0.5 * (double)XD_ * LOG2PI * NSd;
    double tot = (L1 + L234) / (double)S_ + g_acc[2];
    out[0] = (float)(-tot);
}

extern "C" void kernel_launch(void* const* d_in, const int* in_sizes, int n_in,
                              void* d_out, int out_size)
{
    const float* Y            = (const float*)d_in[0];
    const float* We_mu        = (const float*)d_in[1];
    const float* be_mu        = (const float*)d_in[2];
    const float* We_sig       = (const float*)d_in[3];
    const float* be_sig       = (const float*)d_in[4];
    const float* Wd_mu        = (const float*)d_in[5];
    const float* bd_mu        = (const float*)d_in[6];
    const float* Wd_sig       = (const float*)d_in[7];
    const float* bd_sig       = (const float*)d_in[8];
    const float* phi_mus      = (const float*)d_in[9];
    const float* phi_sigs     = (const float*)d_in[10];
    const float* phi_logits   = (const float*)d_in[11];
    const float* theta_mus    = (const float*)d_in[12];
    const float* theta_sigs   = (const float*)d_in[13];
    const float* theta_logits = (const float*)d_in[14];
    const float* u_noise      = (const float*)d_in[15];
    const float* eps_noise    = (const float*)d_in[16];
    const float* temperature  = (const float*)d_in[17];

    encoder_kernel<<<N_ / 64, 256>>>(Y, We_mu, be_mu, We_sig, be_sig);
    mixture_kernel<<<N_ / 2, 128>>>(phi_mus, phi_sigs, phi_logits,
                                    theta_mus, theta_sigs, theta_logits,
                                    u_noise, eps_noise, temperature);
    decoder_kernel<<<dim3(NS_ / 64, YD_ / 64), 256>>>(Y, Wd_mu, bd_mu,
                                                      Wd_sig, bd_sig);
    finalize_kernel<<<1, 1>>>((float*)d_out);
}